// round 6
// baseline (speedup 1.0000x reference)
#include <cuda_runtime.h>
#include <cstdint>

#define H 256
#define W 256
#define K 512
#define Z_THRESHOLD 3.0f
#define EPS 1e-08f

// sqrt(0.5 * log2(e)): folded into inverse scales so gauss = exp2(-(dx'^2+dy'^2))
#define SCALE_C 0.84932180028801904f

#define TPB  512              // threads per block == K
#define GRID ((H * W) / TPB)  // 128 blocks, one pixel per thread, single wave

// ---------------------------------------------------------------------------
// Fused kernel: every block redundantly preps in shared memory:
//   1) per-gaussian eff_w,
//   2) warp-ballot compaction of nonzero-weight keys (zeros are compositing
//      identities; key embeds original idx so the subsequent sort reproduces
//      the exact stable argsort order regardless of compaction order),
//   3) bitonic sort of 128 padded slots (threads 0-127; full-512 fallback),
// then each thread composites one pixel front-to-back over the M active
// sorted gaussians with log2(w) folded into the exp2 argument.
// One wave (128 blocks < #SMs), one launch.
// ---------------------------------------------------------------------------
__global__ void __launch_bounds__(TPB, 1)
fused_kernel(const float* __restrict__ positions,   // [K,3]
             const float* __restrict__ scales,      // [K,3]
             const float* __restrict__ opacity,     // [K]
             const float* __restrict__ intensity,   // [K]
             const float* __restrict__ z_target,    // [1]
             float* __restrict__ out)               // [H*W]
{
    __shared__ unsigned long long sk[K];   // compacted + sort keys
    __shared__ float4 up4[K];   // unsorted: isx, -px*isx, isy, -py*isy
    __shared__ float  uin[K];   // unsorted intensity
    __shared__ float4 sp[K];    // sorted params
    __shared__ float2 swi[K];   // sorted (log2(eff_w), intensity)
    __shared__ int    sCnt;

    const int tid = threadIdx.x;

    if (tid == 0) sCnt = 0;

    // ---- prep: per-gaussian weight + packed params (unsorted) ----
    const float zt  = z_target[0];
    const float px  = positions[tid * 3 + 0];
    const float py  = positions[tid * 3 + 1];
    const float pz  = positions[tid * 3 + 2];
    const float isx = SCALE_C / (scales[tid * 3 + 0] + EPS);
    const float isy = SCALE_C / (scales[tid * 3 + 1] + EPS);
    const float sz  = scales[tid * 3 + 2];

    const float zd = (zt - pz) / (sz + EPS);
    float w = 0.0f;
    if (fabsf(zd) < Z_THRESHOLD) {
        w = opacity[tid] * __expf(-0.5f * zd * zd);
    }

    up4[tid] = make_float4(isx, -px * isx, isy, -py * isy);
    uin[tid] = intensity[tid];
    __syncthreads();   // sCnt=0 + up4/uin visible

    // ---- compaction of nonzero-weight keys ----
    // Pack: ascending uint64 sort == descending eff_w, ascending idx on ties
    // (matches stable jnp.argsort(-eff_w); keys unique via embedded idx).
    const bool active = (w > 0.0f);
    unsigned int wb = __float_as_uint(w);   // w >= 0 so bits are monotone
    unsigned long long key =
        ((unsigned long long)(~wb) << 32) | (unsigned int)tid;

    unsigned int mask = __ballot_sync(0xFFFFFFFFu, active);
    int base = 0;
    if ((tid & 31) == 0 && mask) base = atomicAdd(&sCnt, __popc(mask));
    base = __shfl_sync(0xFFFFFFFFu, base, 0);
    if (active) {
        int pos = base + __popc(mask & ((1u << (tid & 31)) - 1u));
        sk[pos] = key;
    }
    __syncthreads();

    const int M = sCnt;
    // Sort width: 128 normally; full 512 if unusually many active.
    const int NS = (M <= 128) ? 128 : K;

    // Pad remaining slots with MAX keys (sort to the end).
    if (tid >= M && tid < NS) sk[tid] = 0xFFFFFFFFFFFFFFFFull;
    __syncthreads();

    // ---- bitonic sort (ascending) over NS slots; threads >= NS only join
    //      the barriers (tid<NS is warp-uniform: NS is a multiple of 32). ----
    unsigned long long kreg = (tid < NS) ? sk[tid] : 0xFFFFFFFFFFFFFFFFull;
    for (int k = 2; k <= NS; k <<= 1) {
        for (int j = k >> 1; j > 0; j >>= 1) {
            if (j >= 32) {
                if (tid < NS) sk[tid] = kreg;
                __syncthreads();
                if (tid < NS) {
                    unsigned long long b = sk[tid ^ j];
                    bool up      = ((tid & k) == 0);
                    bool lower   = ((tid & j) == 0);
                    bool keepMin = (up == lower);
                    kreg = ((kreg < b) == keepMin) ? kreg : b;
                }
                __syncthreads();
            } else if (tid < NS) {
                unsigned long long b = __shfl_xor_sync(0xFFFFFFFFu, kreg, j);
                bool up      = ((tid & k) == 0);
                bool lower   = ((tid & j) == 0);
                bool keepMin = (up == lower);
                kreg = ((kreg < b) == keepMin) ? kreg : b;
            }
        }
    }

    // ---- gather sorted params; fold log2(w) for the render loop ----
    if (tid < M) {
        int src = (int)(kreg & 0xFFFFFFFFull);
        float wsorted = __uint_as_float(~(unsigned int)(kreg >> 32));
        sp[tid]  = up4[src];
        swi[tid] = make_float2(__log2f(wsorted), uin[src]);
    }
    __syncthreads();

    // ---- render: one pixel per thread ----
    const int p = blockIdx.x * TPB + tid;
    const float fy = (float)(p >> 8);    // row    (positions[:,0])
    const float fx = (float)(p & 255);   // column (positions[:,1])

    float T = 1.0f;
    float A = 0.0f;

    #pragma unroll 4
    for (int j = 0; j < M; ++j) {
        const float4 P  = sp[j];
        const float2 WI = swi[j];

        float dx  = fmaf(fy, P.x, P.y);        // (fy - px) * isx'
        float dy  = fmaf(fx, P.z, P.w);        // (fx - py) * isy'
        float t0  = fmaf(dx, -dx, WI.x);       // log2(w) - dx'^2
        float arg = fmaf(dy, -dy, t0);         // log2(w) - dx'^2 - dy'^2

        float ga;                              // == gauss * eff_w
        asm("ex2.approx.ftz.f32 %0, %1;" : "=f"(ga) : "f"(arg));

        float a  = fminf(ga, 0.99f);
        float ta = T * a;
        A = fmaf(ta, WI.y, A);
        T -= ta;
    }

    out[p] = A;
}

extern "C" void kernel_launch(void* const* d_in, const int* in_sizes, int n_in,
                              void* d_out, int out_size)
{
    const float* positions = (const float*)d_in[0];
    const float* scales    = (const float*)d_in[1];
    const float* opacity   = (const float*)d_in[2];
    const float* intensity = (const float*)d_in[3];
    const float* z_target  = (const float*)d_in[4];
    float* out = (float*)d_out;

    fused_kernel<<<GRID, TPB>>>(positions, scales, opacity, intensity,
                                z_target, out);
}

// round 7
// speedup vs baseline: 1.2620x; 1.2620x over previous
#include <cuda_runtime.h>
#include <cstdint>

#define H 256
#define W 256
#define K 512
#define Z_THRESHOLD 3.0f
#define EPS 1e-08f

// sqrt(0.5 * log2(e)): folded into inverse scales so gauss = exp2(-(dx'^2+dy'^2))
#define SCALE_C 0.84932180028801904f

#define TPB  512              // threads per block == K
#define GRID ((H * W) / TPB)  // 128 blocks, one pixel per thread, single wave

// ---------------------------------------------------------------------------
// Fused kernel, rank-sort version. Every block redundantly:
//   1) computes per-gaussian eff_w + packed params,
//   2) ballot-compacts the M nonzero-weight keys into smem (zeros are
//      compositing identities; keys embed the original index, so ordering
//      information survives compaction exactly),
//   3) rank sort: each of the M threads counts how many compacted keys are
//      smaller than its own (keys unique -> exact permutation == stable
//      argsort(-eff_w)), then scatters its params to sp[rank],
//   4) renders one pixel per thread, front-to-back over the M sorted
//      gaussians with log2(w) folded into the exp2 argument.
// One wave (128 blocks < #SMs), one launch, 3 barriers.
// ---------------------------------------------------------------------------
__global__ void __launch_bounds__(TPB, 1)
fused_kernel(const float* __restrict__ positions,   // [K,3]
             const float* __restrict__ scales,      // [K,3]
             const float* __restrict__ opacity,     // [K]
             const float* __restrict__ intensity,   // [K]
             const float* __restrict__ z_target,    // [1]
             float* __restrict__ out)               // [H*W]
{
    __shared__ unsigned long long sk[K];  // compacted active keys
    __shared__ float4 up4[K];   // unsorted: isx', -px*isx', isy', -py*isy'
    __shared__ float  uin[K];   // unsorted intensity
    __shared__ float4 sp[K];    // rank-ordered params
    __shared__ float2 swi[K];   // rank-ordered (log2(eff_w), intensity)
    __shared__ int    sCnt;

    const int tid = threadIdx.x;

    if (tid == 0) sCnt = 0;

    // ---- prep: per-gaussian weight + packed params (unsorted) ----
    const float zt  = z_target[0];
    const float px  = positions[tid * 3 + 0];
    const float py  = positions[tid * 3 + 1];
    const float pz  = positions[tid * 3 + 2];
    const float isx = SCALE_C / (scales[tid * 3 + 0] + EPS);
    const float isy = SCALE_C / (scales[tid * 3 + 1] + EPS);
    const float sz  = scales[tid * 3 + 2];

    const float zd = (zt - pz) / (sz + EPS);
    float w = 0.0f;
    if (fabsf(zd) < Z_THRESHOLD) {
        w = opacity[tid] * __expf(-0.5f * zd * zd);
    }

    up4[tid] = make_float4(isx, -px * isx, isy, -py * isy);
    uin[tid] = intensity[tid];
    __syncthreads();   // sCnt=0 + up4/uin visible

    // ---- compaction of nonzero-weight keys ----
    // Ascending uint64 order == descending eff_w, ascending idx on ties
    // (matches stable jnp.argsort(-eff_w); keys unique via embedded idx).
    const bool active = (w > 0.0f);
    unsigned int wb = __float_as_uint(w);   // w >= 0 so bits are monotone
    unsigned long long key =
        ((unsigned long long)(~wb) << 32) | (unsigned int)tid;

    unsigned int mask = __ballot_sync(0xFFFFFFFFu, active);
    int base = 0;
    if ((tid & 31) == 0 && mask) base = atomicAdd(&sCnt, __popc(mask));
    base = __shfl_sync(0xFFFFFFFFu, base, 0);
    if (active) {
        int pos = base + __popc(mask & ((1u << (tid & 31)) - 1u));
        sk[pos] = key;
    }
    __syncthreads();

    const int M = sCnt;

    // ---- rank sort: thread t (< M) ranks its compacted key against all M ----
    if (tid < M) {
        const unsigned long long mykey = sk[tid];
        int rank = 0;
        #pragma unroll 4
        for (int j = 0; j < M; ++j) {
            rank += (sk[j] < mykey);   // broadcast LDS, unique keys
        }
        const int src = (int)(mykey & 0xFFFFFFFFull);
        const float ws = __uint_as_float(~(unsigned int)(mykey >> 32));
        sp[rank]  = up4[src];
        swi[rank] = make_float2(__log2f(ws), uin[src]);
    }
    __syncthreads();

    // ---- render: one pixel per thread ----
    const int p = blockIdx.x * TPB + tid;
    const float fy = (float)(p >> 8);    // row    (positions[:,0])
    const float fx = (float)(p & 255);   // column (positions[:,1])

    float T = 1.0f;
    float A = 0.0f;

    #pragma unroll 4
    for (int j = 0; j < M; ++j) {
        const float4 P  = sp[j];
        const float2 WI = swi[j];

        float dx  = fmaf(fy, P.x, P.y);        // (fy - px) * isx'
        float dy  = fmaf(fx, P.z, P.w);        // (fx - py) * isy'
        float t0  = fmaf(dx, -dx, WI.x);       // log2(w) - dx'^2
        float arg = fmaf(dy, -dy, t0);         // log2(w) - dx'^2 - dy'^2

        float ga;                              // == gauss * eff_w
        asm("ex2.approx.ftz.f32 %0, %1;" : "=f"(ga) : "f"(arg));

        float a  = fminf(ga, 0.99f);
        float ta = T * a;
        A = fmaf(ta, WI.y, A);
        T -= ta;
    }

    out[p] = A;
}

extern "C" void kernel_launch(void* const* d_in, const int* in_sizes, int n_in,
                              void* d_out, int out_size)
{
    const float* positions = (const float*)d_in[0];
    const float* scales    = (const float*)d_in[1];
    const float* opacity   = (const float*)d_in[2];
    const float* intensity = (const float*)d_in[3];
    const float* z_target  = (const float*)d_in[4];
    float* out = (float*)d_out;

    fused_kernel<<<GRID, TPB>>>(positions, scales, opacity, intensity,
                                z_target, out);
}